// round 3
// baseline (speedup 1.0000x reference)
#include <cuda_runtime.h>
#include <math.h>

#define TOK    4096
#define DMODEL 768
#define LDX    769
#define NHEAD  12
#define HD     64
#define SEQ    1024
#define NBH    48
#define MLP    3072

// ---------------- scratch (device globals; no allocation allowed) ----------
__device__ float g_h0[TOK * LDX];
__device__ float g_Sq[TOK * DMODEL];
__device__ float g_Sk[TOK * DMODEL];
__device__ float g_Sv[TOK * DMODEL];
__device__ float g_vt[TOK * DMODEL];
__device__ float g_qt[NBH * SEQ];
__device__ float g_kt[NBH * SEQ];
__device__ float g_attncat[TOK * LDX];
__device__ float g_attnt[TOK * NHEAD];
__device__ float g_res[TOK * DMODEL];
__device__ float g_h2[TOK * LDX];
__device__ float g_h3[TOK * (MLP + 1)];
__device__ float g_Sm[TOK * MLP];

// ---------------- helpers --------------------------------------------------
__device__ __forceinline__ float softplusf(float x) {
    return x > 20.f ? x : log1pf(__expf(x));
}

__device__ __forceinline__ float block_sum(float v, float* red) {
#pragma unroll
    for (int o = 16; o > 0; o >>= 1) v += __shfl_xor_sync(0xffffffffu, v, o);
    int w = threadIdx.x >> 5;
    int nw = blockDim.x >> 5;
    if ((threadIdx.x & 31) == 0) red[w] = v;
    __syncthreads();
    float r = 0.f;
    for (int i = 0; i < nw; i++) r += red[i];
    __syncthreads();
    return r;
}

__device__ __forceinline__ float block_max(float v, float* red) {
#pragma unroll
    for (int o = 16; o > 0; o >>= 1) v = fmaxf(v, __shfl_xor_sync(0xffffffffu, v, o));
    int w = threadIdx.x >> 5;
    int nw = blockDim.x >> 5;
    if ((threadIdx.x & 31) == 0) red[w] = v;
    __syncthreads();
    float r = -3.4e38f;
    for (int i = 0; i < nw; i++) r = fmaxf(r, red[i]);
    __syncthreads();
    return r;
}

// ---------------- LayerNorm over 768 spatial dims, write [t, s] (769) ------
__global__ __launch_bounds__(256) void ln_rows_kernel(
    const float* __restrict__ in, int ld, int off,
    const float* __restrict__ gam, const float* __restrict__ bet,
    float* __restrict__ out)
{
    int row = blockIdx.x;
    const float* xr = in + row * ld + off;
    __shared__ float red[8];
    float v[3];
    float s1 = 0.f, s2 = 0.f;
#pragma unroll
    for (int r = 0; r < 3; r++) {
        int c = threadIdx.x + r * 256;
        float x = xr[c];
        v[r] = x; s1 += x; s2 += x * x;
    }
    s1 = block_sum(s1, red);
    s2 = block_sum(s2, red);
    float mu = s1 * (1.f / DMODEL);
    float var = s2 * (1.f / DMODEL) - mu * mu;
    float rstd = rsqrtf(var + 1e-5f);
    float ss = 0.f;
#pragma unroll
    for (int r = 0; r < 3; r++) {
        int c = threadIdx.x + r * 256;
        float nv = (v[r] - mu) * rstd * gam[c] + bet[c];
        out[row * LDX + 1 + c] = nv;
        ss += nv * nv;
    }
    ss = block_sum(ss, red);
    if (threadIdx.x == 0) out[row * LDX] = sqrtf(1.f + ss);
}

// ---------------- fp32 SIMT GEMM: C[M,N] = A[M,K] @ B[N,K]^T ---------------
// 128x128 tile, 256 threads, 8x8 microtile per thread. FFMA-pipe bound.
#define BM 128
#define BN 128
#define BKK 16
__global__ __launch_bounds__(256) void gemm_kernel(
    const float* __restrict__ A, const float* __restrict__ B,
    float* __restrict__ C, int M, int N, int K, int lda, int ldb, int ldc)
{
    __shared__ float As[BKK][BM + 4];
    __shared__ float Bs[BKK][BN + 4];
    int tid = threadIdx.x;
    int tx = tid & 15, ty = tid >> 4;          // 16x16 threads
    int m0 = blockIdx.y * BM;
    int n0 = blockIdx.x * BN;
    float acc[8][8];
#pragma unroll
    for (int i = 0; i < 8; i++)
#pragma unroll
        for (int j = 0; j < 8; j++) acc[i][j] = 0.f;

    for (int k0 = 0; k0 < K; k0 += BKK) {
#pragma unroll
        for (int it = 0; it < 8; it++) {       // 128*16/256 = 8
            int idx = tid + it * 256;
            int m = idx >> 4, k = idx & 15;
            As[k][m] = (k0 + k < K) ? A[(m0 + m) * lda + k0 + k] : 0.f;
        }
#pragma unroll
        for (int it = 0; it < 8; it++) {
            int idx = tid + it * 256;
            int n = idx >> 4, k = idx & 15;
            Bs[k][n] = (k0 + k < K) ? B[(n0 + n) * ldb + k0 + k] : 0.f;
        }
        __syncthreads();
#pragma unroll
        for (int k = 0; k < BKK; k++) {
            float a[8], b[8];
#pragma unroll
            for (int i = 0; i < 8; i++) a[i] = As[k][ty * 8 + i];
#pragma unroll
            for (int j = 0; j < 8; j++) b[j] = Bs[k][tx * 8 + j];
#pragma unroll
            for (int i = 0; i < 8; i++)
#pragma unroll
                for (int j = 0; j < 8; j++) acc[i][j] += a[i] * b[j];
        }
        __syncthreads();
    }
#pragma unroll
    for (int i = 0; i < 8; i++)
#pragma unroll
        for (int j = 0; j < 8; j++)
            C[(m0 + ty * 8 + i) * ldc + n0 + tx * 8 + j] = acc[i][j];
}

// ---------------- QKV epilogue: q_t, k_t, v_tan ----------------------------
__global__ __launch_bounds__(64) void qkv_post_kernel() {
    int gid = blockIdx.x;             // bh*SEQ + i
    int bh = gid >> 10, i = gid & 1023;
    int b = bh / NHEAD, h = bh % NHEAD;
    int off = (b * SEQ + i) * DMODEL + h * HD + threadIdx.x;
    float q = g_Sq[off], k = g_Sk[off], vv = g_Sv[off];
    float sq = q * q, sk = k * k, sv = vv * vv;
#pragma unroll
    for (int o = 16; o > 0; o >>= 1) {
        sq += __shfl_xor_sync(0xffffffffu, sq, o);
        sk += __shfl_xor_sync(0xffffffffu, sk, o);
        sv += __shfl_xor_sync(0xffffffffu, sv, o);
    }
    __shared__ float red[6];
    if ((threadIdx.x & 31) == 0) {
        int w = threadIdx.x >> 5;
        red[w * 3 + 0] = sq; red[w * 3 + 1] = sk; red[w * 3 + 2] = sv;
    }
    __syncthreads();
    float Sq2 = red[0] + red[3], Sk2 = red[1] + red[4], Sv2 = red[2] + red[5];
    if (threadIdx.x == 0) {
        g_qt[gid] = sqrtf(1.f + Sq2);
        g_kt[gid] = sqrtf(1.f + Sk2);
    }
    // logmap0 of v: u = arccosh(max(v_t,1+1e-7)) * v_s / max(||v_s||, 1e-8)
    float vt_time = sqrtf(1.f + Sv2);
    float sn = sqrtf(Sv2);
    float dist = acoshf(fmaxf(vt_time, 1.f + 1e-7f));
    g_vt[off] = vv * (dist / fmaxf(sn, 1e-8f));
}

// ---------------- attention: 8 query rows per CTA, full softmax ------------
// dynamic smem layout (floats):
//   sq[512] | qscal[32] | logit[8192] | ktile[128*65] | red[8] | buf[512]
__global__ __launch_bounds__(128) void attn_kernel(
    const float* __restrict__ alpha_p, const float* __restrict__ tau_p,
    const float* __restrict__ lam_p)
{
    extern __shared__ float smdyn[];
    float* sq    = smdyn;
    float* qscal = smdyn + 512;
    float* logit = smdyn + 544;
    float* ktile = smdyn + 8736;
    float* red   = smdyn + 17056;
    float* buf   = smdyn + 17064;

    int tid = threadIdx.x;
    int bh = blockIdx.y;
    int b = bh / NHEAD, h = bh % NHEAD;
    int i0 = blockIdx.x * 8;
    int tokbase = b * SEQ;

    float tau = softplusf(tau_p[0]);
    float lam = softplusf(lam_p[0]);

    for (int idx = tid; idx < 512; idx += 128) {
        int i = idx >> 6, d = idx & 63;
        sq[idx] = g_Sq[(tokbase + i0 + i) * DMODEL + h * HD + d];
    }
    if (tid < 8) {
        float alpha = softplusf(alpha_p[0]);
        float qt = g_qt[bh * SEQ + i0 + tid];
        float coshOQ = fmaxf(qt, 1.f + 1e-7f);
        float c_t = fminf(acoshf(coshOQ), 40.f);
        float sOQ = sinhf(c_t);
        float Bv = alpha * c_t / (1.f + alpha * c_t);
        qscal[tid * 4 + 0] = qt;
        qscal[tid * 4 + 1] = coshOQ;
        qscal[tid * 4 + 2] = 1.f / sOQ;
        qscal[tid * 4 + 3] = Bv;
    }
    __syncthreads();
    float qt_r[8], cOQ_r[8], isOQ_r[8], Bv_r[8];
#pragma unroll
    for (int i = 0; i < 8; i++) {
        qt_r[i]   = qscal[i * 4 + 0];
        cOQ_r[i]  = qscal[i * 4 + 1];
        isOQ_r[i] = qscal[i * 4 + 2];
        Bv_r[i]   = qscal[i * 4 + 3];
    }

    // pass 1: logits
    for (int jt = 0; jt < SEQ; jt += 128) {
        __syncthreads();                 // protect ktile from previous readers
        for (int idx = tid; idx < 128 * 64; idx += 128) {
            int j = idx >> 6, d = idx & 63;
            ktile[j * 65 + d] = g_Sk[(tokbase + jt + j) * DMODEL + h * HD + d];
        }
        ktile[tid * 65 + 64] = g_kt[bh * SEQ + jt + tid];
        __syncthreads();
        int j = tid;
        float dot[8];
#pragma unroll
        for (int i = 0; i < 8; i++) dot[i] = 0.f;
#pragma unroll 8
        for (int d = 0; d < 64; d++) {
            float kv = ktile[j * 65 + d];
#pragma unroll
            for (int i = 0; i < 8; i++) dot[i] += sq[i * 64 + d] * kv;
        }
        float kt = ktile[j * 65 + 64];
        float coshOK = fmaxf(kt, 1.f + 1e-7f);
#pragma unroll
        for (int i = 0; i < 8; i++) {
            float raw_cosh = fmaxf(qt_r[i] * kt - dot[i], 1.f);
            bool is_self = raw_cosh < 1.f + 1e-5f;
            float safe_cosh = is_self ? 2.f : raw_cosh;
            float dist = acoshf(safe_cosh);
            // sinh(arccosh(x)) = sqrt(x^2-1)
            float invSinhQK = rsqrtf(safe_cosh * safe_cosh - 1.f);
            float rawZ = (raw_cosh * cOQ_r[i] - coshOK) * isOQ_r[i] * invSinhQK;
            float Z = is_self ? 1.f : fminf(fmaxf(rawZ, -1.f), 1.f);
            float dL = fminf(dist, 40.f);
            float lp = -lam * log1pf(dL * dL);
            float ent = softplusf(Bv_r[i] + Z - 0.1f); // const softplus(-m) cancels in softmax
            logit[i * 1024 + jt + j] = lp - tau * ent;
        }
    }
    __syncthreads();

    // softmax per query row (in place: logit -> exp values)
    float sums[8];
#pragma unroll
    for (int i = 0; i < 8; i++) {
        float mx = -3.4e38f;
        for (int jj = tid; jj < SEQ; jj += 128) mx = fmaxf(mx, logit[i * 1024 + jj]);
        mx = block_max(mx, red);
        float s = 0.f;
        for (int jj = tid; jj < SEQ; jj += 128) {
            float e = __expf(logit[i * 1024 + jj] - mx);
            logit[i * 1024 + jj] = e;
            s += e;
        }
        sums[i] = block_sum(s, red);
    }

    // pass 2: agg = sum_j p_j * v_tan[j]
    int d = tid & 63, grp = tid >> 6;
    float acc[8];
#pragma unroll
    for (int i = 0; i < 8; i++) acc[i] = 0.f;
    for (int j = grp; j < SEQ; j += 2) {
        float v = g_vt[(tokbase + j) * DMODEL + h * HD + d];
#pragma unroll
        for (int i = 0; i < 8; i++) acc[i] += logit[i * 1024 + j] * v;
    }
    if (grp == 0) {
#pragma unroll
        for (int i = 0; i < 8; i++) buf[i * 64 + d] = acc[i];
    }
    __syncthreads();
    if (grp == 1) {
#pragma unroll
        for (int i = 0; i < 8; i++) buf[i * 64 + d] += acc[i];
    }
    __syncthreads();

    // expmap0 + write concat layout
#pragma unroll
    for (int i = 0; i < 8; i++) {
        float scale = 1.f / sums[i];   // sum(score)+1e-8 : 1e-8 sub-ulp at 1.0 in fp32
        float a = (tid < 64) ? buf[i * 64 + tid] * scale : 0.f;
        float n2 = block_sum(a * a, red);
        float nn = sqrtf(n2);
        float tt = coshf(nn);
        float sfac = sinhf(nn) / fmaxf(nn, 1e-8f);
        if (tid < 64)
            g_attncat[(tokbase + i0 + i) * LDX + 1 + h * HD + tid] = a * sfac;
        if (tid == 0)
            g_attnt[(tokbase + i0 + i) * NHEAD + h] = tt;
    }
}

// ---------------- t_new = sqrt(sum_h t_h^2 - 11) ---------------------------
__global__ void attn_time_kernel() {
    int t = blockIdx.x * 256 + threadIdx.x;
    if (t < TOK) {
        float s = 0.f;
#pragma unroll
        for (int hh = 0; hh < NHEAD; hh++) { float a = g_attnt[t * NHEAD + hh]; s += a * a; }
        g_attncat[t * LDX] = sqrtf(s - (float)(NHEAD - 1));
    }
}

// ---------------- residual: res = So + x_s ---------------------------------
__global__ void resid_kernel(const float* __restrict__ x) {
    int idx = blockIdx.x * 256 + threadIdx.x;
    if (idx < TOK * DMODEL) {
        int row = idx / DMODEL, c = idx % DMODEL;
        g_res[idx] = g_Sq[idx] + x[row * LDX + 1 + c];
    }
}

// ---------------- GELU (exact) + add_time over 3072 ------------------------
__global__ __launch_bounds__(256) void gelu_time_kernel() {
    int row = blockIdx.x;
    __shared__ float red[8];
    float ss = 0.f;
    for (int c = threadIdx.x; c < MLP; c += 256) {
        float v = g_Sm[row * MLP + c];
        float ge = 0.5f * v * (1.f + erff(v * 0.70710678118654752f));
        g_h3[row * (MLP + 1) + 1 + c] = ge;
        ss += ge * ge;
    }
    ss = block_sum(ss, red);
    if (threadIdx.x == 0) g_h3[row * (MLP + 1)] = sqrtf(1.f + ss);
}

// ---------------- final: out = add_time(Sm2 + res) -------------------------
__global__ __launch_bounds__(256) void final_kernel(float* __restrict__ out) {
    int row = blockIdx.x;
    __shared__ float red[8];
    float vals[3]; float ss = 0.f;
#pragma unroll
    for (int r = 0; r < 3; r++) {
        int c = threadIdx.x + r * 256;
        float f = g_Sk[row * DMODEL + c] + g_res[row * DMODEL + c];
        vals[r] = f; ss += f * f;
    }
    ss = block_sum(ss, red);
#pragma unroll
    for (int r = 0; r < 3; r++) {
        int c = threadIdx.x + r * 256;
        out[row * LDX + 1 + c] = vals[r];
    }
    if (threadIdx.x == 0) out[row * LDX] = sqrtf(1.f + ss);
}

// ---------------- host -----------------------------------------------------
extern "C" void kernel_launch(void* const* d_in, const int* in_sizes, int n_in,
                              void* d_out, int out_size)
{
    const float* x     = (const float*)d_in[0];
    const float* Wq    = (const float*)d_in[1];
    const float* Wk    = (const float*)d_in[2];
    const float* Wv    = (const float*)d_in[3];
    const float* Wo    = (const float*)d_in[4];
    const float* g1    = (const float*)d_in[5];
    const float* b1    = (const float*)d_in[6];
    const float* g2    = (const float*)d_in[7];
    const float* b2    = (const float*)d_in[8];
    const float* Wm1   = (const float*)d_in[9];
    const float* Wm2   = (const float*)d_in[10];
    const float* alpha = (const float*)d_in[11];
    const float* tau   = (const float*)d_in[12];
    const float* lam   = (const float*)d_in[13];
    float* out = (float*)d_out;

    const int ATTN_SMEM = 17576 * 4;
    cudaFuncSetAttribute(attn_kernel, cudaFuncAttributeMaxDynamicSharedMemorySize, ATTN_SMEM);

    void *ah0, *aSq, *aSk, *aSv, *aSm, *acat, *ah2, *ah3, *ares;
    cudaGetSymbolAddress(&ah0,  g_h0);
    cudaGetSymbolAddress(&aSq,  g_Sq);
    cudaGetSymbolAddress(&aSk,  g_Sk);
    cudaGetSymbolAddress(&aSv,  g_Sv);
    cudaGetSymbolAddress(&aSm,  g_Sm);
    cudaGetSymbolAddress(&acat, g_attncat);
    cudaGetSymbolAddress(&ah2,  g_h2);
    cudaGetSymbolAddress(&ah3,  g_h3);
    cudaGetSymbolAddress(&ares, g_res);

    // 1. LN1
    ln_rows_kernel<<<TOK, 256>>>(x, LDX, 1, g1, b1, (float*)ah0);

    // 2. QKV projections (S = h0 @ W^T)
    dim3 g768(DMODEL / BN, TOK / BM);
    gemm_kernel<<<g768, 256>>>((const float*)ah0, Wq, (float*)aSq, TOK, DMODEL, LDX, LDX, LDX, DMODEL);
    gemm_kernel<<<g768, 256>>>((const float*)ah0, Wk, (float*)aSk, TOK, DMODEL, LDX, LDX, LDX, DMODEL);
    gemm_kernel<<<g768, 256>>>((const float*)ah0, Wv, (float*)aSv, TOK, DMODEL, LDX, LDX, LDX, DMODEL);

    // 3. q_t, k_t, v_tan
    qkv_post_kernel<<<NBH * SEQ, 64>>>();

    // 4. attention (8 query rows / CTA)
    dim3 gattn(SEQ / 8, NBH);
    attn_kernel<<<gattn, 128, ATTN_SMEM>>>(alpha, tau, lam);
    attn_time_kernel<<<(TOK + 255) / 256, 256>>>();

    // 5. output projection (So reuses g_Sq)
    gemm_kernel<<<g768, 256>>>((const float*)acat, Wo, (float*)aSq, TOK, DMODEL, LDX, LDX, LDX, DMODEL);

    // 6. residual + LN2
    resid_kernel<<<(TOK * DMODEL + 255) / 256, 256>>>(x);
    ln_rows_kernel<<<TOK, 256>>>((const float*)ares, DMODEL, 0, g2, b2, (float*)ah2);

    // 7. MLP up + GELU + add_time
    dim3 gm1(MLP / BN, TOK / BM);
    gemm_kernel<<<gm1, 256>>>((const float*)ah2, Wm1, (float*)aSm, TOK, MLP, LDX, LDX, LDX, MLP);
    gelu_time_kernel<<<TOK, 256>>>();

    // 8. MLP down (Sm2 reuses g_Sk)
    gemm_kernel<<<g768, 256>>>((const float*)ah3, Wm2, (float*)aSk, TOK, DMODEL, MLP + 1, MLP + 1, MLP + 1, DMODEL);

    // 9. final residual + add_time
    final_kernel<<<TOK, 256>>>(out);
}

// round 4
// speedup vs baseline: 1.3580x; 1.3580x over previous
#include <cuda_runtime.h>
#include <math.h>
#include <stdint.h>

#define TOK    4096
#define DMODEL 768
#define LDX    769
#define NHEAD  12
#define HD     64
#define SEQ    1024
#define NBH    48
#define MLP    3072

// ---------------- scratch (device globals; no allocation allowed) ----------
__device__ float g_h0[TOK * LDX];
__device__ float g_Sq[TOK * DMODEL];
__device__ float g_Sk[TOK * DMODEL];
__device__ float g_Sv[TOK * DMODEL];
__device__ float g_vt[TOK * DMODEL];
__device__ float g_qt[NBH * SEQ];
__device__ float g_kt[NBH * SEQ];
__device__ float g_attncat[TOK * LDX];
__device__ float g_attnt[TOK * NHEAD];
__device__ float g_res[TOK * DMODEL];
__device__ float g_h2[TOK * LDX];
__device__ float g_h3[TOK * (MLP + 1)];
__device__ float g_Sm[TOK * MLP];

// ---------------- helpers --------------------------------------------------
__device__ __forceinline__ float softplusf(float x) {
    return x > 20.f ? x : log1pf(__expf(x));
}

__device__ __forceinline__ uint32_t f2tf32(float v) {
    uint32_t u;
    asm("cvt.rna.tf32.f32 %0, %1;" : "=r"(u) : "f"(v));
    return u;
}

__device__ __forceinline__ float block_sum(float v, float* red) {
#pragma unroll
    for (int o = 16; o > 0; o >>= 1) v += __shfl_xor_sync(0xffffffffu, v, o);
    int w = threadIdx.x >> 5;
    int nw = blockDim.x >> 5;
    if ((threadIdx.x & 31) == 0) red[w] = v;
    __syncthreads();
    float r = 0.f;
    for (int i = 0; i < nw; i++) r += red[i];
    __syncthreads();
    return r;
}

__device__ __forceinline__ float block_max(float v, float* red) {
#pragma unroll
    for (int o = 16; o > 0; o >>= 1) v = fmaxf(v, __shfl_xor_sync(0xffffffffu, v, o));
    int w = threadIdx.x >> 5;
    int nw = blockDim.x >> 5;
    if ((threadIdx.x & 31) == 0) red[w] = v;
    __syncthreads();
    float r = -3.4e38f;
    for (int i = 0; i < nw; i++) r = fmaxf(r, red[i]);
    __syncthreads();
    return r;
}

// ---------------- LayerNorm over 768 spatial dims, write [t, s] (769) ------
__global__ __launch_bounds__(256) void ln_rows_kernel(
    const float* __restrict__ in, int ld, int off,
    const float* __restrict__ gam, const float* __restrict__ bet,
    float* __restrict__ out)
{
    int row = blockIdx.x;
    const float* xr = in + row * ld + off;
    __shared__ float red[8];
    float v[3];
    float s1 = 0.f, s2 = 0.f;
#pragma unroll
    for (int r = 0; r < 3; r++) {
        int c = threadIdx.x + r * 256;
        float x = xr[c];
        v[r] = x; s1 += x; s2 += x * x;
    }
    s1 = block_sum(s1, red);
    s2 = block_sum(s2, red);
    float mu = s1 * (1.f / DMODEL);
    float var = s2 * (1.f / DMODEL) - mu * mu;
    float rstd = rsqrtf(var + 1e-5f);
    float ss = 0.f;
#pragma unroll
    for (int r = 0; r < 3; r++) {
        int c = threadIdx.x + r * 256;
        float nv = (v[r] - mu) * rstd * gam[c] + bet[c];
        out[row * LDX + 1 + c] = nv;
        ss += nv * nv;
    }
    ss = block_sum(ss, red);
    if (threadIdx.x == 0) out[row * LDX] = sqrtf(1.f + ss);
}

// ---------------- tf32 tensor-core GEMM: C[M,N] = A[M,K] @ B[N,K]^T --------
// 128x128 CTA tile, 8 warps (4x2), each warp 32(m) x 64(n) via m16n8k8.
// Smem m-major [128][36]: pad 4 -> conflict-free fills AND fragment loads.
#define BM 128
#define BN 128
#define BK 32
#define SKP 36
__global__ __launch_bounds__(256, 2) void gemm_tf32_kernel(
    const float* __restrict__ A, const float* __restrict__ B,
    float* __restrict__ C, int M, int N, int K, int lda, int ldb, int ldc)
{
    __shared__ uint32_t As[BM * SKP];
    __shared__ uint32_t Bs[BN * SKP];

    int tid  = threadIdx.x;
    int lane = tid & 31;
    int warp = tid >> 5;
    int warp_m = (warp >> 1) * 32;   // 0,32,64,96
    int warp_n = (warp & 1) * 64;    // 0,64
    int m0 = blockIdx.y * BM;
    int n0 = blockIdx.x * BN;

    int frow = lane >> 2;            // 0..7
    int fk   = lane & 3;             // 0..3

    float acc[2][8][4];
#pragma unroll
    for (int i = 0; i < 2; i++)
#pragma unroll
        for (int j = 0; j < 8; j++)
#pragma unroll
            for (int c = 0; c < 4; c++) acc[i][j][c] = 0.f;

    for (int k0 = 0; k0 < K; k0 += BK) {
        // fill: each thread 16 elements of A and 16 of B; consecutive tid ->
        // consecutive k (coalesced global, conflict-free stores)
#pragma unroll
        for (int it = 0; it < 16; it++) {
            int idx = tid + it * 256;
            int m = idx >> 5, k = idx & 31;
            float va = (k0 + k < K) ? A[(m0 + m) * lda + k0 + k] : 0.f;
            As[m * SKP + k] = f2tf32(va);
        }
#pragma unroll
        for (int it = 0; it < 16; it++) {
            int idx = tid + it * 256;
            int n = idx >> 5, k = idx & 31;
            float vb = (k0 + k < K) ? B[(n0 + n) * ldb + k0 + k] : 0.f;
            Bs[n * SKP + k] = f2tf32(vb);
        }
        __syncthreads();

#pragma unroll
        for (int ks = 0; ks < 4; ks++) {
            int kb = ks * 8 + fk;
            uint32_t a[2][4];
#pragma unroll
            for (int i = 0; i < 2; i++) {
                int mr = warp_m + i * 16 + frow;
                a[i][0] = As[mr * SKP + kb];
                a[i][1] = As[(mr + 8) * SKP + kb];
                a[i][2] = As[mr * SKP + kb + 4];
                a[i][3] = As[(mr + 8) * SKP + kb + 4];
            }
#pragma unroll
            for (int j = 0; j < 8; j++) {
                int nr = warp_n + j * 8 + frow;
                uint32_t b0 = Bs[nr * SKP + kb];
                uint32_t b1 = Bs[nr * SKP + kb + 4];
#pragma unroll
                for (int i = 0; i < 2; i++) {
                    asm volatile(
                        "mma.sync.aligned.m16n8k8.row.col.f32.tf32.tf32.f32 "
                        "{%0,%1,%2,%3}, {%4,%5,%6,%7}, {%8,%9}, {%0,%1,%2,%3};"
                        : "+f"(acc[i][j][0]), "+f"(acc[i][j][1]),
                          "+f"(acc[i][j][2]), "+f"(acc[i][j][3])
                        : "r"(a[i][0]), "r"(a[i][1]), "r"(a[i][2]), "r"(a[i][3]),
                          "r"(b0), "r"(b1));
                }
            }
        }
        __syncthreads();
    }

    // epilogue
#pragma unroll
    for (int i = 0; i < 2; i++) {
#pragma unroll
        for (int j = 0; j < 8; j++) {
            int row = m0 + warp_m + i * 16 + frow;
            int col = n0 + warp_n + j * 8 + fk * 2;
            C[row * ldc + col]           = acc[i][j][0];
            C[row * ldc + col + 1]       = acc[i][j][1];
            C[(row + 8) * ldc + col]     = acc[i][j][2];
            C[(row + 8) * ldc + col + 1] = acc[i][j][3];
        }
    }
}

// ---------------- QKV epilogue: q_t, k_t, v_tan ----------------------------
__global__ __launch_bounds__(64) void qkv_post_kernel() {
    int gid = blockIdx.x;             // bh*SEQ + i
    int bh = gid >> 10, i = gid & 1023;
    int b = bh / NHEAD, h = bh % NHEAD;
    int off = (b * SEQ + i) * DMODEL + h * HD + threadIdx.x;
    float q = g_Sq[off], k = g_Sk[off], vv = g_Sv[off];
    float sq = q * q, sk = k * k, sv = vv * vv;
#pragma unroll
    for (int o = 16; o > 0; o >>= 1) {
        sq += __shfl_xor_sync(0xffffffffu, sq, o);
        sk += __shfl_xor_sync(0xffffffffu, sk, o);
        sv += __shfl_xor_sync(0xffffffffu, sv, o);
    }
    __shared__ float red[6];
    if ((threadIdx.x & 31) == 0) {
        int w = threadIdx.x >> 5;
        red[w * 3 + 0] = sq; red[w * 3 + 1] = sk; red[w * 3 + 2] = sv;
    }
    __syncthreads();
    float Sq2 = red[0] + red[3], Sk2 = red[1] + red[4], Sv2 = red[2] + red[5];
    if (threadIdx.x == 0) {
        g_qt[gid] = sqrtf(1.f + Sq2);
        g_kt[gid] = sqrtf(1.f + Sk2);
    }
    // logmap0 of v: u = arccosh(max(v_t,1+1e-7)) * v_s / max(||v_s||, 1e-8)
    float vt_time = sqrtf(1.f + Sv2);
    float sn = sqrtf(Sv2);
    float dist = acoshf(fmaxf(vt_time, 1.f + 1e-7f));
    g_vt[off] = vv * (dist / fmaxf(sn, 1e-8f));
}

// ---------------- attention: 8 query rows per CTA, full softmax ------------
// dynamic smem layout (floats):
//   sq[512] | qscal[32] | logit[8192] | ktile[128*65] | red[8] | buf[512]
__global__ __launch_bounds__(128) void attn_kernel(
    const float* __restrict__ alpha_p, const float* __restrict__ tau_p,
    const float* __restrict__ lam_p)
{
    extern __shared__ float smdyn[];
    float* sq    = smdyn;
    float* qscal = smdyn + 512;
    float* logit = smdyn + 544;
    float* ktile = smdyn + 8736;
    float* red   = smdyn + 17056;
    float* buf   = smdyn + 17064;

    int tid = threadIdx.x;
    int bh = blockIdx.y;
    int b = bh / NHEAD, h = bh % NHEAD;
    int i0 = blockIdx.x * 8;
    int tokbase = b * SEQ;

    float tau = softplusf(tau_p[0]);
    float lam = softplusf(lam_p[0]);

    for (int idx = tid; idx < 512; idx += 128) {
        int i = idx >> 6, d = idx & 63;
        sq[idx] = g_Sq[(tokbase + i0 + i) * DMODEL + h * HD + d];
    }
    if (tid < 8) {
        float alpha = softplusf(alpha_p[0]);
        float qt = g_qt[bh * SEQ + i0 + tid];
        float coshOQ = fmaxf(qt, 1.f + 1e-7f);
        float c_t = fminf(acoshf(coshOQ), 40.f);
        float sOQ = sinhf(c_t);
        float Bv = alpha * c_t / (1.f + alpha * c_t);
        qscal[tid * 4 + 0] = qt;
        qscal[tid * 4 + 1] = coshOQ;
        qscal[tid * 4 + 2] = 1.f / sOQ;
        qscal[tid * 4 + 3] = Bv;
    }
    __syncthreads();
    float qt_r[8], cOQ_r[8], isOQ_r[8], Bv_r[8];
#pragma unroll
    for (int i = 0; i < 8; i++) {
        qt_r[i]   = qscal[i * 4 + 0];
        cOQ_r[i]  = qscal[i * 4 + 1];
        isOQ_r[i] = qscal[i * 4 + 2];
        Bv_r[i]   = qscal[i * 4 + 3];
    }

    // pass 1: logits
    for (int jt = 0; jt < SEQ; jt += 128) {
        __syncthreads();                 // protect ktile from previous readers
        for (int idx = tid; idx < 128 * 64; idx += 128) {
            int j = idx >> 6, d = idx & 63;
            ktile[j * 65 + d] = g_Sk[(tokbase + jt + j) * DMODEL + h * HD + d];
        }
        ktile[tid * 65 + 64] = g_kt[bh * SEQ + jt + tid];
        __syncthreads();
        int j = tid;
        float dot[8];
#pragma unroll
        for (int i = 0; i < 8; i++) dot[i] = 0.f;
#pragma unroll 8
        for (int d = 0; d < 64; d++) {
            float kv = ktile[j * 65 + d];
#pragma unroll
            for (int i = 0; i < 8; i++) dot[i] += sq[i * 64 + d] * kv;
        }
        float kt = ktile[j * 65 + 64];
        float coshOK = fmaxf(kt, 1.f + 1e-7f);
#pragma unroll
        for (int i = 0; i < 8; i++) {
            float raw_cosh = fmaxf(qt_r[i] * kt - dot[i], 1.f);
            bool is_self = raw_cosh < 1.f + 1e-5f;
            float safe_cosh = is_self ? 2.f : raw_cosh;
            float dist = acoshf(safe_cosh);
            // sinh(arccosh(x)) = sqrt(x^2-1)
            float invSinhQK = rsqrtf(safe_cosh * safe_cosh - 1.f);
            float rawZ = (raw_cosh * cOQ_r[i] - coshOK) * isOQ_r[i] * invSinhQK;
            float Z = is_self ? 1.f : fminf(fmaxf(rawZ, -1.f), 1.f);
            float dL = fminf(dist, 40.f);
            float lp = -lam * log1pf(dL * dL);
            float ent = softplusf(Bv_r[i] + Z - 0.1f); // const softplus(-m) cancels in softmax
            logit[i * 1024 + jt + j] = lp - tau * ent;
        }
    }
    __syncthreads();

    // softmax per query row (in place: logit -> exp values)
    float sums[8];
#pragma unroll
    for (int i = 0; i < 8; i++) {
        float mx = -3.4e38f;
        for (int jj = tid; jj < SEQ; jj += 128) mx = fmaxf(mx, logit[i * 1024 + jj]);
        mx = block_max(mx, red);
        float s = 0.f;
        for (int jj = tid; jj < SEQ; jj += 128) {
            float e = __expf(logit[i * 1024 + jj] - mx);
            logit[i * 1024 + jj] = e;
            s += e;
        }
        sums[i] = block_sum(s, red);
    }

    // pass 2: agg = sum_j p_j * v_tan[j]
    int d = tid & 63, grp = tid >> 6;
    float acc[8];
#pragma unroll
    for (int i = 0; i < 8; i++) acc[i] = 0.f;
    for (int j = grp; j < SEQ; j += 2) {
        float v = g_vt[(tokbase + j) * DMODEL + h * HD + d];
#pragma unroll
        for (int i = 0; i < 8; i++) acc[i] += logit[i * 1024 + j] * v;
    }
    if (grp == 0) {
#pragma unroll
        for (int i = 0; i < 8; i++) buf[i * 64 + d] = acc[i];
    }
    __syncthreads();
    if (grp == 1) {
#pragma unroll
        for (int i = 0; i < 8; i++) buf[i * 64 + d] += acc[i];
    }
    __syncthreads();

    // expmap0 + write concat layout
#pragma unroll
    for (int i = 0; i < 8; i++) {
        float scale = 1.f / sums[i];   // sum(score)+1e-8 : 1e-8 sub-ulp at 1.0 in fp32
        float a = (tid < 64) ? buf[i * 64 + tid] * scale : 0.f;
        float n2 = block_sum(a * a, red);
        float nn = sqrtf(n2);
        float tt = coshf(nn);
        float sfac = sinhf(nn) / fmaxf(nn, 1e-8f);
        if (tid < 64)
            g_attncat[(tokbase + i0 + i) * LDX + 1 + h * HD + tid] = a * sfac;
        if (tid == 0)
            g_attnt[(tokbase + i0 + i) * NHEAD + h] = tt;
    }
}

// ---------------- t_new = sqrt(sum_h t_h^2 - 11) ---------------------------
__global__ void attn_time_kernel() {
    int t = blockIdx.x * 256 + threadIdx.x;
    if (t < TOK) {
        float s = 0.f;
#pragma unroll
        for (int hh = 0; hh < NHEAD; hh++) { float a = g_attnt[t * NHEAD + hh]; s += a * a; }
        g_attncat[t * LDX] = sqrtf(s - (float)(NHEAD - 1));
    }
}

// ---------------- residual: res = So + x_s ---------------------------------
__global__ void resid_kernel(const float* __restrict__ x) {
    int idx = blockIdx.x * 256 + threadIdx.x;
    if (idx < TOK * DMODEL) {
        int row = idx / DMODEL, c = idx % DMODEL;
        g_res[idx] = g_Sq[idx] + x[row * LDX + 1 + c];
    }
}

// ---------------- GELU (exact) + add_time over 3072 ------------------------
__global__ __launch_bounds__(256) void gelu_time_kernel() {
    int row = blockIdx.x;
    __shared__ float red[8];
    float ss = 0.f;
    for (int c = threadIdx.x; c < MLP; c += 256) {
        float v = g_Sm[row * MLP + c];
        float ge = 0.5f * v * (1.f + erff(v * 0.70710678118654752f));
        g_h3[row * (MLP + 1) + 1 + c] = ge;
        ss += ge * ge;
    }
    ss = block_sum(ss, red);
    if (threadIdx.x == 0) g_h3[row * (MLP + 1)] = sqrtf(1.f + ss);
}

// ---------------- final: out = add_time(Sm2 + res) -------------------------
__global__ __launch_bounds__(256) void final_kernel(float* __restrict__ out) {
    int row = blockIdx.x;
    __shared__ float red[8];
    float vals[3]; float ss = 0.f;
#pragma unroll
    for (int r = 0; r < 3; r++) {
        int c = threadIdx.x + r * 256;
        float f = g_Sk[row * DMODEL + c] + g_res[row * DMODEL + c];
        vals[r] = f; ss += f * f;
    }
    ss = block_sum(ss, red);
#pragma unroll
    for (int r = 0; r < 3; r++) {
        int c = threadIdx.x + r * 256;
        out[row * LDX + 1 + c] = vals[r];
    }
    if (threadIdx.x == 0) out[row * LDX] = sqrtf(1.f + ss);
}

// ---------------- host -----------------------------------------------------
extern "C" void kernel_launch(void* const* d_in, const int* in_sizes, int n_in,
                              void* d_out, int out_size)
{
    const float* x     = (const float*)d_in[0];
    const float* Wq    = (const float*)d_in[1];
    const float* Wk    = (const float*)d_in[2];
    const float* Wv    = (const float*)d_in[3];
    const float* Wo    = (const float*)d_in[4];
    const float* g1    = (const float*)d_in[5];
    const float* b1    = (const float*)d_in[6];
    const float* g2    = (const float*)d_in[7];
    const float* b2    = (const float*)d_in[8];
    const float* Wm1   = (const float*)d_in[9];
    const float* Wm2   = (const float*)d_in[10];
    const float* alpha = (const float*)d_in[11];
    const float* tau   = (const float*)d_in[12];
    const float* lam   = (const float*)d_in[13];
    float* out = (float*)d_out;

    const int ATTN_SMEM = 17576 * 4;
    cudaFuncSetAttribute(attn_kernel, cudaFuncAttributeMaxDynamicSharedMemorySize, ATTN_SMEM);

    void *ah0, *aSq, *aSk, *aSv, *aSm, *acat, *ah2, *ah3, *ares;
    cudaGetSymbolAddress(&ah0,  g_h0);
    cudaGetSymbolAddress(&aSq,  g_Sq);
    cudaGetSymbolAddress(&aSk,  g_Sk);
    cudaGetSymbolAddress(&aSv,  g_Sv);
    cudaGetSymbolAddress(&aSm,  g_Sm);
    cudaGetSymbolAddress(&acat, g_attncat);
    cudaGetSymbolAddress(&ah2,  g_h2);
    cudaGetSymbolAddress(&ah3,  g_h3);
    cudaGetSymbolAddress(&ares, g_res);

    // 1. LN1
    ln_rows_kernel<<<TOK, 256>>>(x, LDX, 1, g1, b1, (float*)ah0);

    // 2. QKV projections (S = h0 @ W^T)
    dim3 g768(DMODEL / BN, TOK / BM);
    gemm_tf32_kernel<<<g768, 256>>>((const float*)ah0, Wq, (float*)aSq, TOK, DMODEL, LDX, LDX, LDX, DMODEL);
    gemm_tf32_kernel<<<g768, 256>>>((const float*)ah0, Wk, (float*)aSk, TOK, DMODEL, LDX, LDX, LDX, DMODEL);
    gemm_tf32_kernel<<<g768, 256>>>((const float*)ah0, Wv, (float*)aSv, TOK, DMODEL, LDX, LDX, LDX, DMODEL);

    // 3. q_t, k_t, v_tan
    qkv_post_kernel<<<NBH * SEQ, 64>>>();

    // 4. attention (8 query rows / CTA)
    dim3 gattn(SEQ / 8, NBH);
    attn_kernel<<<gattn, 128, ATTN_SMEM>>>(alpha, tau, lam);
    attn_time_kernel<<<(TOK + 255) / 256, 256>>>();

    // 5. output projection (So reuses g_Sq)
    gemm_tf32_kernel<<<g768, 256>>>((const float*)acat, Wo, (float*)aSq, TOK, DMODEL, LDX, LDX, LDX, DMODEL);

    // 6. residual + LN2
    resid_kernel<<<(TOK * DMODEL + 255) / 256, 256>>>(x);
    ln_rows_kernel<<<TOK, 256>>>((const float*)ares, DMODEL, 0, g2, b2, (float*)ah2);

    // 7. MLP up + GELU + add_time
    dim3 gm1(MLP / BN, TOK / BM);
    gemm_tf32_kernel<<<gm1, 256>>>((const float*)ah2, Wm1, (float*)aSm, TOK, MLP, LDX, LDX, LDX, MLP);
    gelu_time_kernel<<<TOK, 256>>>();

    // 8. MLP down (Sm2 reuses g_Sk)
    gemm_tf32_kernel<<<g768, 256>>>((const float*)ah3, Wm2, (float*)aSk, TOK, DMODEL, MLP + 1, MLP + 1, MLP + 1, DMODEL);

    // 9. final residual + add_time
    final_kernel<<<TOK, 256>>>(out);
}

// round 9
// speedup vs baseline: 1.6438x; 1.2105x over previous
#include <cuda_runtime.h>
#include <math.h>
#include <stdint.h>

#define TOK    4096
#define DMODEL 768
#define LDX    769
#define NHEAD  12
#define HD     64
#define SEQ    1024
#define NBH    48
#define MLP    3072

// ---------------- scratch (device globals; no allocation allowed) ----------
__device__ float g_h0[TOK * LDX];
__device__ float g_Sq[TOK * DMODEL];
__device__ float g_Sk[TOK * DMODEL];
__device__ float g_Sv[TOK * DMODEL];
__device__ float g_vt[TOK * DMODEL];
__device__ float g_qt[NBH * SEQ];
__device__ float g_kt[NBH * SEQ];
__device__ float g_attncat[TOK * LDX];
__device__ float g_attnt[TOK * NHEAD];
__device__ float g_res[TOK * DMODEL];
__device__ float g_h2[TOK * LDX];
__device__ float g_h3[TOK * (MLP + 1)];
__device__ float g_Sm[TOK * MLP];

// ---------------- helpers --------------------------------------------------
__device__ __forceinline__ float softplusf(float x) {
    return x > 20.f ? x : log1pf(__expf(x));
}

__device__ __forceinline__ uint32_t f2tf32(float v) {
    uint32_t u;
    asm("cvt.rna.tf32.f32 %0, %1;" : "=r"(u) : "f"(v));
    return u;
}

__device__ __forceinline__ float block_sum(float v, float* red) {
#pragma unroll
    for (int o = 16; o > 0; o >>= 1) v += __shfl_xor_sync(0xffffffffu, v, o);
    int w = threadIdx.x >> 5;
    int nw = blockDim.x >> 5;
    if ((threadIdx.x & 31) == 0) red[w] = v;
    __syncthreads();
    float r = 0.f;
    for (int i = 0; i < nw; i++) r += red[i];
    __syncthreads();
    return r;
}

__device__ __forceinline__ float block_max(float v, float* red) {
#pragma unroll
    for (int o = 16; o > 0; o >>= 1) v = fmaxf(v, __shfl_xor_sync(0xffffffffu, v, o));
    int w = threadIdx.x >> 5;
    int nw = blockDim.x >> 5;
    if ((threadIdx.x & 31) == 0) red[w] = v;
    __syncthreads();
    float r = -3.4e38f;
    for (int i = 0; i < nw; i++) r = fmaxf(r, red[i]);
    __syncthreads();
    return r;
}

// ---------------- LayerNorm over 768 spatial dims, write [t, s] (769) ------
__global__ __launch_bounds__(256) void ln_rows_kernel(
    const float* __restrict__ in, int ld, int off,
    const float* __restrict__ gam, const float* __restrict__ bet,
    float* __restrict__ out)
{
    int row = blockIdx.x;
    const float* xr = in + row * ld + off;
    __shared__ float red[8];
    float v[3];
    float s1 = 0.f, s2 = 0.f;
#pragma unroll
    for (int r = 0; r < 3; r++) {
        int c = threadIdx.x + r * 256;
        float x = xr[c];
        v[r] = x; s1 += x; s2 += x * x;
    }
    s1 = block_sum(s1, red);
    s2 = block_sum(s2, red);
    float mu = s1 * (1.f / DMODEL);
    float var = s2 * (1.f / DMODEL) - mu * mu;
    float rstd = rsqrtf(var + 1e-5f);
    float ss = 0.f;
#pragma unroll
    for (int r = 0; r < 3; r++) {
        int c = threadIdx.x + r * 256;
        float nv = (v[r] - mu) * rstd * gam[c] + bet[c];
        out[row * LDX + 1 + c] = nv;
        ss += nv * nv;
    }
    ss = block_sum(ss, red);
    if (threadIdx.x == 0) out[row * LDX] = sqrtf(1.f + ss);
}

// ---------------- tf32 tensor-core GEMM (double-buffered) ------------------
// C[M,N] = A[M,K] @ B[N,K]^T. 128x128 CTA tile, 8 warps (4x2), warp 32x64.
#define BM 128
#define BN 128
#define BK 32
#define SKP 36
#define TILEU (BM * SKP)            // u32 per buffer

struct GemmPtrs { const float* B; float* C; };

__device__ __forceinline__ void gemm_body(
    const float* __restrict__ A, const float* __restrict__ B,
    float* __restrict__ C, int K, int lda, int ldb, int ldc,
    uint32_t* As, uint32_t* Bs, int m0, int n0)
{
    int tid  = threadIdx.x;
    int lane = tid & 31;
    int warp = tid >> 5;
    int warp_m = (warp >> 1) * 32;
    int warp_n = (warp & 1) * 64;
    int frow = lane >> 2;
    int fk   = lane & 3;
    int lm = tid >> 5;       // row index this thread fills (base), 0..7 per it
    int lk = tid & 31;       // k index this thread fills

    float acc[2][8][4];
#pragma unroll
    for (int i = 0; i < 2; i++)
#pragma unroll
        for (int j = 0; j < 8; j++)
#pragma unroll
            for (int c = 0; c < 4; c++) acc[i][j][c] = 0.f;

    int nT = (K + BK - 1) / BK;
    float aReg[16], bReg[16];

    // prologue: load tile 0 into regs, store to buffer 0
#pragma unroll
    for (int it = 0; it < 16; it++) {
        int m = lm + it * 8;
        aReg[it] = (lk < K) ? A[(m0 + m) * lda + lk] : 0.f;
        bReg[it] = (lk < K) ? B[(n0 + m) * ldb + lk] : 0.f;
    }
#pragma unroll
    for (int it = 0; it < 16; it++) {
        int m = lm + it * 8;
        As[m * SKP + lk] = f2tf32(aReg[it]);
        Bs[m * SKP + lk] = f2tf32(bReg[it]);
    }
    __syncthreads();

    for (int t = 0; t < nT; t++) {
        uint32_t* Ab = As + (t & 1) * TILEU;
        uint32_t* Bb = Bs + (t & 1) * TILEU;

        if (t + 1 < nT) {
            int k0 = (t + 1) * BK;
#pragma unroll
            for (int it = 0; it < 16; it++) {
                int m = lm + it * 8;
                int kk = k0 + lk;
                aReg[it] = (kk < K) ? A[(m0 + m) * lda + kk] : 0.f;
                bReg[it] = (kk < K) ? B[(n0 + m) * ldb + kk] : 0.f;
            }
        }

#pragma unroll
        for (int ks = 0; ks < 4; ks++) {
            int kb = ks * 8 + fk;
            uint32_t a[2][4];
#pragma unroll
            for (int i = 0; i < 2; i++) {
                int mr = warp_m + i * 16 + frow;
                a[i][0] = Ab[mr * SKP + kb];
                a[i][1] = Ab[(mr + 8) * SKP + kb];
                a[i][2] = Ab[mr * SKP + kb + 4];
                a[i][3] = Ab[(mr + 8) * SKP + kb + 4];
            }
#pragma unroll
            for (int j = 0; j < 8; j++) {
                int nr = warp_n + j * 8 + frow;
                uint32_t b0 = Bb[nr * SKP + kb];
                uint32_t b1 = Bb[nr * SKP + kb + 4];
#pragma unroll
                for (int i = 0; i < 2; i++) {
                    asm volatile(
                        "mma.sync.aligned.m16n8k8.row.col.f32.tf32.tf32.f32 "
                        "{%0,%1,%2,%3}, {%4,%5,%6,%7}, {%8,%9}, {%0,%1,%2,%3};"
                        : "+f"(acc[i][j][0]), "+f"(acc[i][j][1]),
                          "+f"(acc[i][j][2]), "+f"(acc[i][j][3])
                        : "r"(a[i][0]), "r"(a[i][1]), "r"(a[i][2]), "r"(a[i][3]),
                          "r"(b0), "r"(b1));
                }
            }
        }

        if (t + 1 < nT) {
            uint32_t* An = As + ((t + 1) & 1) * TILEU;
            uint32_t* Bn = Bs + ((t + 1) & 1) * TILEU;
#pragma unroll
            for (int it = 0; it < 16; it++) {
                int m = lm + it * 8;
                An[m * SKP + lk] = f2tf32(aReg[it]);
                Bn[m * SKP + lk] = f2tf32(bReg[it]);
            }
            __syncthreads();
        }
    }

#pragma unroll
    for (int i = 0; i < 2; i++) {
#pragma unroll
        for (int j = 0; j < 8; j++) {
            int row = m0 + warp_m + i * 16 + frow;
            int col = n0 + warp_n + j * 8 + fk * 2;
            C[row * ldc + col]           = acc[i][j][0];
            C[row * ldc + col + 1]       = acc[i][j][1];
            C[(row + 8) * ldc + col]     = acc[i][j][2];
            C[(row + 8) * ldc + col + 1] = acc[i][j][3];
        }
    }
}

__global__ __launch_bounds__(256, 2) void gemm_tf32_kernel(
    const float* __restrict__ A, const float* __restrict__ B,
    float* __restrict__ C, int K, int lda, int ldb, int ldc)
{
    extern __shared__ uint32_t smemU[];
    gemm_body(A, B, C, K, lda, ldb, ldc,
              smemU, smemU + 2 * TILEU, blockIdx.y * BM, blockIdx.x * BN);
}

// merged QKV: blockIdx.z selects (weight, dest)
__global__ __launch_bounds__(256, 2) void gemm_tf32_qkv_kernel(
    const float* __restrict__ A,
    const float* __restrict__ Wq, const float* __restrict__ Wk, const float* __restrict__ Wv,
    float* __restrict__ Sq, float* __restrict__ Sk, float* __restrict__ Sv)
{
    extern __shared__ uint32_t smemU[];
    const float* B = (blockIdx.z == 0) ? Wq : (blockIdx.z == 1) ? Wk : Wv;
    float* C       = (blockIdx.z == 0) ? Sq : (blockIdx.z == 1) ? Sk : Sv;
    gemm_body(A, B, C, LDX, LDX, LDX, DMODEL,
              smemU, smemU + 2 * TILEU, blockIdx.y * BM, blockIdx.x * BN);
}

// ---------------- QKV epilogue: q_t, k_t, v_tan ----------------------------
__global__ __launch_bounds__(64) void qkv_post_kernel() {
    int gid = blockIdx.x;             // bh*SEQ + i
    int bh = gid >> 10, i = gid & 1023;
    int b = bh / NHEAD, h = bh % NHEAD;
    int off = (b * SEQ + i) * DMODEL + h * HD + threadIdx.x;
    float q = g_Sq[off], k = g_Sk[off], vv = g_Sv[off];
    float sq = q * q, sk = k * k, sv = vv * vv;
#pragma unroll
    for (int o = 16; o > 0; o >>= 1) {
        sq += __shfl_xor_sync(0xffffffffu, sq, o);
        sk += __shfl_xor_sync(0xffffffffu, sk, o);
        sv += __shfl_xor_sync(0xffffffffu, sv, o);
    }
    __shared__ float red[6];
    if ((threadIdx.x & 31) == 0) {
        int w = threadIdx.x >> 5;
        red[w * 3 + 0] = sq; red[w * 3 + 1] = sk; red[w * 3 + 2] = sv;
    }
    __syncthreads();
    float Sq2 = red[0] + red[3], Sk2 = red[1] + red[4], Sv2 = red[2] + red[5];
    if (threadIdx.x == 0) {
        g_qt[gid] = sqrtf(1.f + Sq2);
        g_kt[gid] = sqrtf(1.f + Sk2);
    }
    float vt_time = sqrtf(1.f + Sv2);
    float sn = sqrtf(Sv2);
    float dist = acoshf(fmaxf(vt_time, 1.f + 1e-7f));
    g_vt[off] = vv * (dist / fmaxf(sn, 1e-8f));
}

// ---------------- attention: 8 query rows per CTA, full softmax ------------
// dyn smem floats: sq[512] | qscal[32] | logit[8192] | ktile[128*68] | red[8] | buf[512]
#define KTP 68
__global__ __launch_bounds__(128) void attn_kernel(
    const float* __restrict__ alpha_p, const float* __restrict__ tau_p,
    const float* __restrict__ lam_p)
{
    extern __shared__ float smdyn[];
    float* sq    = smdyn;
    float* qscal = smdyn + 512;
    float* logit = smdyn + 544;
    float* ktile = smdyn + 8736;
    float* red   = smdyn + 17440;
    float* buf   = smdyn + 17448;

    int tid = threadIdx.x;
    int bh = blockIdx.y;
    int b = bh / NHEAD, h = bh % NHEAD;
    int i0 = blockIdx.x * 8;
    int tokbase = b * SEQ;

    float tau = softplusf(tau_p[0]);
    float lam = softplusf(lam_p[0]);

    for (int idx = tid; idx < 512; idx += 128) {
        int i = idx >> 6, d = idx & 63;
        sq[idx] = g_Sq[(tokbase + i0 + i) * DMODEL + h * HD + d];
    }
    if (tid < 8) {
        float alpha = softplusf(alpha_p[0]);
        float qt = g_qt[bh * SEQ + i0 + tid];
        float coshOQ = fmaxf(qt, 1.f + 1e-7f);
        float c_t = fminf(acoshf(coshOQ), 40.f);
        float sOQ = sinhf(c_t);
        float Bv = alpha * c_t / (1.f + alpha * c_t);
        qscal[tid * 4 + 0] = qt;
        qscal[tid * 4 + 1] = coshOQ;
        qscal[tid * 4 + 2] = 1.f / sOQ;
        qscal[tid * 4 + 3] = Bv;
    }
    __syncthreads();
    float qt_r[8], cOQ_r[8], isOQ_r[8], Bv_r[8];
#pragma unroll
    for (int i = 0; i < 8; i++) {
        qt_r[i]   = qscal[i * 4 + 0];
        cOQ_r[i]  = qscal[i * 4 + 1];
        isOQ_r[i] = qscal[i * 4 + 2];
        Bv_r[i]   = qscal[i * 4 + 3];
    }

    // pass 1: logits
    for (int jt = 0; jt < SEQ; jt += 128) {
        __syncthreads();
        for (int idx = tid; idx < 128 * 64; idx += 128) {
            int j = idx >> 6, d = idx & 63;
            ktile[j * KTP + d] = g_Sk[(tokbase + jt + j) * DMODEL + h * HD + d];
        }
        ktile[tid * KTP + 64] = g_kt[bh * SEQ + jt + tid];
        __syncthreads();
        int j = tid;
        float dot[8];
#pragma unroll
        for (int i = 0; i < 8; i++) dot[i] = 0.f;
        const float4* kt4 = reinterpret_cast<const float4*>(ktile + j * KTP);
        const float4* sq4 = reinterpret_cast<const float4*>(sq);
#pragma unroll 4
        for (int d4 = 0; d4 < 16; d4++) {
            float4 kv = kt4[d4];
#pragma unroll
            for (int i = 0; i < 8; i++) {
                float4 qv = sq4[i * 16 + d4];
                dot[i] += qv.x * kv.x + qv.y * kv.y + qv.z * kv.z + qv.w * kv.w;
            }
        }
        float kt = ktile[j * KTP + 64];
        float coshOK = fmaxf(kt, 1.f + 1e-7f);
#pragma unroll
        for (int i = 0; i < 8; i++) {
            float raw_cosh = fmaxf(qt_r[i] * kt - dot[i], 1.f);
            bool is_self = raw_cosh < 1.f + 1e-5f;
            float safe_cosh = is_self ? 2.f : raw_cosh;
            float t2 = safe_cosh * safe_cosh - 1.f;     // >= ~2e-5
            float invs = rsqrtf(t2);                    // 1/sinh(dist)
            float s = t2 * invs;                        // sinh(dist)
            float dist = __logf(safe_cosh + s);         // acosh
            float rawZ = (raw_cosh * cOQ_r[i] - coshOK) * isOQ_r[i] * invs;
            float Z = is_self ? 1.f : fminf(fmaxf(rawZ, -1.f), 1.f);
            float dL = fminf(dist, 40.f);
            float lp = -lam * __logf(1.f + dL * dL);
            float xe = Bv_r[i] + Z - 0.1f;
            float ent = __logf(1.f + __expf(xe));       // softplus; const term cancels
            logit[i * 1024 + jt + j] = lp - tau * ent;
        }
    }
    __syncthreads();

    // softmax per query row (in place)
    float sums[8];
#pragma unroll
    for (int i = 0; i < 8; i++) {
        float mx = -3.4e38f;
        for (int jj = tid; jj < SEQ; jj += 128) mx = fmaxf(mx, logit[i * 1024 + jj]);
        mx = block_max(mx, red);
        float s = 0.f;
        for (int jj = tid; jj < SEQ; jj += 128) {
            float e = __expf(logit[i * 1024 + jj] - mx);
            logit[i * 1024 + jj] = e;
            s += e;
        }
        sums[i] = block_sum(s, red);
    }

    // pass 2: agg = sum_j p_j * v_tan[j]
    int d = tid & 63, grp = tid >> 6;
    float acc[8];
#pragma unroll
    for (int i = 0; i < 8; i++) acc[i] = 0.f;
    for (int j = grp; j < SEQ; j += 2) {
        float v = g_vt[(tokbase + j) * DMODEL + h * HD + d];
#pragma unroll
        for (int i = 0; i < 8; i++) acc[i] += logit[i * 1024 + j] * v;
    }
    if (grp == 0) {
#pragma unroll
        for (int i = 0; i < 8; i++) buf[i * 64 + d] = acc[i];
    }
    __syncthreads();
    if (grp == 1) {
#pragma unroll
        for (int i = 0; i < 8; i++) buf[i * 64 + d] += acc[i];
    }
    __syncthreads();

    // expmap0 + write concat layout
#pragma unroll
    for (int i = 0; i < 8; i++) {
        float scale = 1.f / sums[i];
        float a = (tid < 64) ? buf[i * 64 + tid] * scale : 0.f;
        float n2 = block_sum(a * a, red);
        float nn = sqrtf(n2);
        float tt = coshf(nn);
        float sfac = sinhf(nn) / fmaxf(nn, 1e-8f);
        if (tid < 64)
            g_attncat[(tokbase + i0 + i) * LDX + 1 + h * HD + tid] = a * sfac;
        if (tid == 0)
            g_attnt[(tokbase + i0 + i) * NHEAD + h] = tt;
    }
}

// ---------------- t_new = sqrt(sum_h t_h^2 - 11) ---------------------------
__global__ void attn_time_kernel() {
    int t = blockIdx.x * 256 + threadIdx.x;
    if (t < TOK) {
        float s = 0.f;
#pragma unroll
        for (int hh = 0; hh < NHEAD; hh++) { float a = g_attnt[t * NHEAD + hh]; s += a * a; }
        g_attncat[t * LDX] = sqrtf(s - (float)(NHEAD - 1));
    }
}

// ---------------- residual: res = So + x_s ---------------------------------
__global__ void resid_kernel(const float* __restrict__ x) {
    int idx = blockIdx.x * 256 + threadIdx.x;
    if (idx < TOK * DMODEL) {
        int row = idx / DMODEL, c = idx % DMODEL;
        g_res[idx] = g_Sq[idx] + x[row * LDX + 1 + c];
    }
}

// ---------------- GELU (exact) + add_time over 3072 ------------------------
__global__ __launch_bounds__(256) void gelu_time_kernel() {
    int row = blockIdx.x;
    __shared__ float red[8];
    float ss = 0.f;
    for (int c = threadIdx.x; c < MLP; c += 256) {
        float v = g_Sm[row * MLP + c];
        float ge = 0.5f * v * (1.f + erff(v * 0.70710678118654752f));
        g_h3[row * (MLP + 1) + 1 + c] = ge;
        ss += ge * ge;
    }
    ss = block_sum(ss, red);
    if (threadIdx.x == 0) g_h3[row * (MLP + 1)] = sqrtf(1.f + ss);
}

// ---------------- final: out = add_time(Sm2 + res) -------------------------
__global__ __launch_bounds__(256) void final_kernel(float* __restrict__ out) {
    int row = blockIdx.x;
    __shared__ float red[8];
    float vals[3]; float ss = 0.f;
#pragma unroll
    for (int r = 0; r < 3; r++) {
        int c = threadIdx.x + r * 256;
        float f = g_Sk[row * DMODEL + c] + g_res[row * DMODEL + c];
        vals[r] = f; ss += f * f;
    }
    ss = block_sum(ss, red);
#pragma unroll
    for (int r = 0; r < 3; r++) {
        int c = threadIdx.x + r * 256;
        out[row * LDX + 1 + c] = vals[r];
    }
    if (threadIdx.x == 0) out[row * LDX] = sqrtf(1.f + ss);
}

// ---------------- host -----------------------------------------------------
extern "C" void kernel_launch(void* const* d_in, const int* in_sizes, int n_in,
                              void* d_out, int out_size)
{
    const float* x     = (const float*)d_in[0];
    const float* Wq    = (const float*)d_in[1];
    const float* Wk    = (const float*)d_in[2];
    const float* Wv    = (const float*)d_in[3];
    const float* Wo    = (const float*)d_in[4];
    const float* g1    = (const float*)d_in[5];
    const float* b1    = (const float*)d_in[6];
    const float* g2    = (const float*)d_in[7];
    const float* b2    = (const float*)d_in[8];
    const float* Wm1   = (const float*)d_in[9];
    const float* Wm2   = (const float*)d_in[10];
    const float* alpha = (const float*)d_in[11];
    const float* tau   = (const float*)d_in[12];
    const float* lam   = (const float*)d_in[13];
    float* out = (float*)d_out;

    const int ATTN_SMEM = 17960 * 4;
    const int GEMM_SMEM = 4 * TILEU * 4;     // 2 buffers x (As+Bs)
    cudaFuncSetAttribute(attn_kernel, cudaFuncAttributeMaxDynamicSharedMemorySize, ATTN_SMEM);
    cudaFuncSetAttribute(gemm_tf32_kernel, cudaFuncAttributeMaxDynamicSharedMemorySize, GEMM_SMEM);
    cudaFuncSetAttribute(gemm_tf32_qkv_kernel, cudaFuncAttributeMaxDynamicSharedMemorySize, GEMM_SMEM);

    void *ah0, *aSq, *aSk, *aSv, *aSm, *acat, *ah2, *ah3, *ares;
    cudaGetSymbolAddress(&ah0,  g_h0);
    cudaGetSymbolAddress(&aSq,  g_Sq);
    cudaGetSymbolAddress(&aSk,  g_Sk);
    cudaGetSymbolAddress(&aSv,  g_Sv);
    cudaGetSymbolAddress(&aSm,  g_Sm);
    cudaGetSymbolAddress(&acat, g_attncat);
    cudaGetSymbolAddress(&ah2,  g_h2);
    cudaGetSymbolAddress(&ah3,  g_h3);
    cudaGetSymbolAddress(&ares, g_res);

    // 1. LN1
    ln_rows_kernel<<<TOK, 256>>>(x, LDX, 1, g1, b1, (float*)ah0);

    // 2. QKV projections, one launch (z = q/k/v)
    dim3 gqkv(DMODEL / BN, TOK / BM, 3);
    gemm_tf32_qkv_kernel<<<gqkv, 256, GEMM_SMEM>>>(
        (const float*)ah0, Wq, Wk, Wv, (float*)aSq, (float*)aSk, (float*)aSv);

    // 3. q_t, k_t, v_tan
    qkv_post_kernel<<<NBH * SEQ, 64>>>();

    // 4. attention (8 query rows / CTA)
    dim3 gattn(SEQ / 8, NBH);
    attn_kernel<<<gattn, 128, ATTN_SMEM>>>(alpha, tau, lam);
    attn_time_kernel<<<(TOK + 255) / 256, 256>>>();

    // 5. output projection (So reuses g_Sq)
    dim3 g768(DMODEL / BN, TOK / BM);
    gemm_tf32_kernel<<<g768, 256, GEMM_SMEM>>>((const float*)acat, Wo, (float*)aSq, LDX, LDX, LDX, DMODEL);

    // 6. residual + LN2
    resid_kernel<<<(TOK * DMODEL + 255) / 256, 256>>>(x);
    ln_rows_kernel<<<TOK, 256>>>((const float*)ares, DMODEL, 0, g2, b2, (float*)ah2);

    // 7. MLP up + GELU + add_time
    dim3 gm1(MLP / BN, TOK / BM);
    gemm_tf32_kernel<<<gm1, 256, GEMM_SMEM>>>((const float*)ah2, Wm1, (float*)aSm, LDX, LDX, LDX, MLP);
    gelu_time_kernel<<<TOK, 256>>>();

    // 8. MLP down (Sm2 reuses g_Sk)
    gemm_tf32_kernel<<<g768, 256, GEMM_SMEM>>>((const float*)ah3, Wm2, (float*)aSk, MLP + 1, MLP + 1, MLP + 1, DMODEL);

    // 9. final residual + add_time
    final_kernel<<<TOK, 256>>>(out);
}

// round 10
// speedup vs baseline: 2.8702x; 1.7461x over previous
#include <cuda_runtime.h>
#include <math.h>
#include <stdint.h>

#define TOK    4096
#define DMODEL 768
#define LDX    769
#define NHEAD  12
#define HD     64
#define SEQ    1024
#define NBH    48
#define MLP    3072

// ---------------- scratch (device globals; no allocation allowed) ----------
__device__ float g_h0[TOK * LDX];
__device__ float g_Sq[TOK * DMODEL];
__device__ float g_Sk[TOK * DMODEL];
__device__ float g_Sv[TOK * DMODEL];
__device__ float g_vt[TOK * DMODEL];
__device__ float g_qt[NBH * SEQ];
__device__ float g_kt[NBH * SEQ];
__device__ float g_attncat[TOK * LDX];
__device__ float g_attnt[TOK * NHEAD];
__device__ float g_res[TOK * DMODEL];
__device__ float g_h2[TOK * LDX];
__device__ float g_h3[TOK * (MLP + 1)];
__device__ float g_Sm[TOK * MLP];

// ---------------- helpers --------------------------------------------------
__device__ __forceinline__ float softplusf(float x) {
    return x > 20.f ? x : log1pf(__expf(x));
}

__device__ __forceinline__ uint32_t f2tf32(float v) {
    uint32_t u;
    asm("cvt.rna.tf32.f32 %0, %1;" : "=r"(u) : "f"(v));
    return u;
}

__device__ __forceinline__ unsigned long long fma_f32x2(
    unsigned long long a, unsigned long long b, unsigned long long c) {
    unsigned long long d;
    asm("fma.rn.f32x2 %0, %1, %2, %3;" : "=l"(d) : "l"(a), "l"(b), "l"(c));
    return d;
}
__device__ __forceinline__ unsigned long long pack_f32x2(float lo, float hi) {
    unsigned long long r;
    asm("mov.b64 %0, {%1, %2};" : "=l"(r) : "f"(lo), "f"(hi));
    return r;
}
__device__ __forceinline__ void unpack_f32x2(unsigned long long v, float& lo, float& hi) {
    asm("mov.b64 {%0, %1}, %2;" : "=f"(lo), "=f"(hi) : "l"(v));
}

__device__ __forceinline__ float block_sum(float v, float* red) {
#pragma unroll
    for (int o = 16; o > 0; o >>= 1) v += __shfl_xor_sync(0xffffffffu, v, o);
    int w = threadIdx.x >> 5;
    int nw = blockDim.x >> 5;
    if ((threadIdx.x & 31) == 0) red[w] = v;
    __syncthreads();
    float r = 0.f;
    for (int i = 0; i < nw; i++) r += red[i];
    __syncthreads();
    return r;
}

// ---------------- LayerNorm over 768 spatial dims, write [t, s] (769) ------
__global__ __launch_bounds__(256) void ln_rows_kernel(
    const float* __restrict__ in, int ld, int off,
    const float* __restrict__ gam, const float* __restrict__ bet,
    float* __restrict__ out)
{
    int row = blockIdx.x;
    const float* xr = in + row * ld + off;
    __shared__ float red[8];
    float v[3];
    float s1 = 0.f, s2 = 0.f;
#pragma unroll
    for (int r = 0; r < 3; r++) {
        int c = threadIdx.x + r * 256;
        float x = xr[c];
        v[r] = x; s1 += x; s2 += x * x;
    }
    s1 = block_sum(s1, red);
    s2 = block_sum(s2, red);
    float mu = s1 * (1.f / DMODEL);
    float var = s2 * (1.f / DMODEL) - mu * mu;
    float rstd = rsqrtf(var + 1e-5f);
    float ss = 0.f;
#pragma unroll
    for (int r = 0; r < 3; r++) {
        int c = threadIdx.x + r * 256;
        float nv = (v[r] - mu) * rstd * gam[c] + bet[c];
        out[row * LDX + 1 + c] = nv;
        ss += nv * nv;
    }
    ss = block_sum(ss, red);
    if (threadIdx.x == 0) out[row * LDX] = sqrtf(1.f + ss);
}

// ---------------- tf32 tensor-core GEMM (double-buffered) ------------------
#define BM 128
#define BN 128
#define BK 32
#define SKP 36
#define TILEU (BM * SKP)

__device__ __forceinline__ void gemm_body(
    const float* __restrict__ A, const float* __restrict__ B,
    float* __restrict__ C, int K, int lda, int ldb, int ldc,
    uint32_t* As, uint32_t* Bs, int m0, int n0)
{
    int tid  = threadIdx.x;
    int lane = tid & 31;
    int warp = tid >> 5;
    int warp_m = (warp >> 1) * 32;
    int warp_n = (warp & 1) * 64;
    int frow = lane >> 2;
    int fk   = lane & 3;
    int lm = tid >> 5;
    int lk = tid & 31;

    float acc[2][8][4];
#pragma unroll
    for (int i = 0; i < 2; i++)
#pragma unroll
        for (int j = 0; j < 8; j++)
#pragma unroll
            for (int c = 0; c < 4; c++) acc[i][j][c] = 0.f;

    int nT = (K + BK - 1) / BK;
    float aReg[16], bReg[16];

#pragma unroll
    for (int it = 0; it < 16; it++) {
        int m = lm + it * 8;
        aReg[it] = (lk < K) ? A[(m0 + m) * lda + lk] : 0.f;
        bReg[it] = (lk < K) ? B[(n0 + m) * ldb + lk] : 0.f;
    }
#pragma unroll
    for (int it = 0; it < 16; it++) {
        int m = lm + it * 8;
        As[m * SKP + lk] = f2tf32(aReg[it]);
        Bs[m * SKP + lk] = f2tf32(bReg[it]);
    }
    __syncthreads();

    for (int t = 0; t < nT; t++) {
        uint32_t* Ab = As + (t & 1) * TILEU;
        uint32_t* Bb = Bs + (t & 1) * TILEU;

        if (t + 1 < nT) {
            int k0 = (t + 1) * BK;
#pragma unroll
            for (int it = 0; it < 16; it++) {
                int m = lm + it * 8;
                int kk = k0 + lk;
                aReg[it] = (kk < K) ? A[(m0 + m) * lda + kk] : 0.f;
                bReg[it] = (kk < K) ? B[(n0 + m) * ldb + kk] : 0.f;
            }
        }

#pragma unroll
        for (int ks = 0; ks < 4; ks++) {
            int kb = ks * 8 + fk;
            uint32_t a[2][4];
#pragma unroll
            for (int i = 0; i < 2; i++) {
                int mr = warp_m + i * 16 + frow;
                a[i][0] = Ab[mr * SKP + kb];
                a[i][1] = Ab[(mr + 8) * SKP + kb];
                a[i][2] = Ab[mr * SKP + kb + 4];
                a[i][3] = Ab[(mr + 8) * SKP + kb + 4];
            }
#pragma unroll
            for (int j = 0; j < 8; j++) {
                int nr = warp_n + j * 8 + frow;
                uint32_t b0 = Bb[nr * SKP + kb];
                uint32_t b1 = Bb[nr * SKP + kb + 4];
#pragma unroll
                for (int i = 0; i < 2; i++) {
                    asm volatile(
                        "mma.sync.aligned.m16n8k8.row.col.f32.tf32.tf32.f32 "
                        "{%0,%1,%2,%3}, {%4,%5,%6,%7}, {%8,%9}, {%0,%1,%2,%3};"
                        : "+f"(acc[i][j][0]), "+f"(acc[i][j][1]),
                          "+f"(acc[i][j][2]), "+f"(acc[i][j][3])
                        : "r"(a[i][0]), "r"(a[i][1]), "r"(a[i][2]), "r"(a[i][3]),
                          "r"(b0), "r"(b1));
                }
            }
        }

        if (t + 1 < nT) {
            uint32_t* An = As + ((t + 1) & 1) * TILEU;
            uint32_t* Bn = Bs + ((t + 1) & 1) * TILEU;
#pragma unroll
            for (int it = 0; it < 16; it++) {
                int m = lm + it * 8;
                An[m * SKP + lk] = f2tf32(aReg[it]);
                Bn[m * SKP + lk] = f2tf32(bReg[it]);
            }
            __syncthreads();
        }
    }

#pragma unroll
    for (int i = 0; i < 2; i++) {
#pragma unroll
        for (int j = 0; j < 8; j++) {
            int row = m0 + warp_m + i * 16 + frow;
            int col = n0 + warp_n + j * 8 + fk * 2;
            C[row * ldc + col]           = acc[i][j][0];
            C[row * ldc + col + 1]       = acc[i][j][1];
            C[(row + 8) * ldc + col]     = acc[i][j][2];
            C[(row + 8) * ldc + col + 1] = acc[i][j][3];
        }
    }
}

__global__ __launch_bounds__(256, 2) void gemm_tf32_kernel(
    const float* __restrict__ A, const float* __restrict__ B,
    float* __restrict__ C, int K, int lda, int ldb, int ldc)
{
    extern __shared__ uint32_t smemU[];
    gemm_body(A, B, C, K, lda, ldb, ldc,
              smemU, smemU + 2 * TILEU, blockIdx.y * BM, blockIdx.x * BN);
}

__global__ __launch_bounds__(256, 2) void gemm_tf32_qkv_kernel(
    const float* __restrict__ A,
    const float* __restrict__ Wq, const float* __restrict__ Wk, const float* __restrict__ Wv,
    float* __restrict__ Sq, float* __restrict__ Sk, float* __restrict__ Sv)
{
    extern __shared__ uint32_t smemU[];
    const float* B = (blockIdx.z == 0) ? Wq : (blockIdx.z == 1) ? Wk : Wv;
    float* C       = (blockIdx.z == 0) ? Sq : (blockIdx.z == 1) ? Sk : Sv;
    gemm_body(A, B, C, LDX, LDX, LDX, DMODEL,
              smemU, smemU + 2 * TILEU, blockIdx.y * BM, blockIdx.x * BN);
}

// ---------------- QKV epilogue: q_t, k_t, v_tan ----------------------------
__global__ __launch_bounds__(64) void qkv_post_kernel() {
    int gid = blockIdx.x;             // bh*SEQ + i
    int bh = gid >> 10, i = gid & 1023;
    int b = bh / NHEAD, h = bh % NHEAD;
    int off = (b * SEQ + i) * DMODEL + h * HD + threadIdx.x;
    float q = g_Sq[off], k = g_Sk[off], vv = g_Sv[off];
    float sq = q * q, sk = k * k, sv = vv * vv;
#pragma unroll
    for (int o = 16; o > 0; o >>= 1) {
        sq += __shfl_xor_sync(0xffffffffu, sq, o);
        sk += __shfl_xor_sync(0xffffffffu, sk, o);
        sv += __shfl_xor_sync(0xffffffffu, sv, o);
    }
    __shared__ float red[6];
    if ((threadIdx.x & 31) == 0) {
        int w = threadIdx.x >> 5;
        red[w * 3 + 0] = sq; red[w * 3 + 1] = sk; red[w * 3 + 2] = sv;
    }
    __syncthreads();
    float Sq2 = red[0] + red[3], Sk2 = red[1] + red[4], Sv2 = red[2] + red[5];
    if (threadIdx.x == 0) {
        g_qt[gid] = sqrtf(1.f + Sq2);
        g_kt[gid] = sqrtf(1.f + Sk2);
    }
    float vt_time = sqrtf(1.f + Sv2);
    float sn = sqrtf(Sv2);
    float dist = acoshf(fmaxf(vt_time, 1.f + 1e-7f));
    g_vt[off] = vv * (dist / fmaxf(sn, 1e-8f));
}

// ---------------- attention v2: one query per thread, online softmax -------
// CTA: 128 threads = 128 queries, one (b,h). K/V chunks staged in smem,
// broadcast-read by all lanes (same j). q + accumulators in registers (f32x2).
// dyn smem floats: kc[128*64] | vc[128*64] | ktc[128]
#define CHK 128
__global__ __launch_bounds__(128, 3) void attn_kernel(
    const float* __restrict__ alpha_p, const float* __restrict__ tau_p,
    const float* __restrict__ lam_p)
{
    extern __shared__ float smdyn[];
    float* kc  = smdyn;
    float* vc  = smdyn + CHK * 64;
    float* ktc = smdyn + 2 * CHK * 64;

    int tid = threadIdx.x;
    int bh = blockIdx.y;
    int b = bh / NHEAD, h = bh % NHEAD;
    int i = blockIdx.x * 128 + tid;      // this thread's query
    int tokbase = b * SEQ;

    float tau = softplusf(tau_p[0]);
    float lam = softplusf(lam_p[0]);
    float alpha = softplusf(alpha_p[0]);

    // load q into registers (f32x2 packed)
    const float* qrow = g_Sq + (tokbase + i) * DMODEL + h * HD;
    unsigned long long q2[32];
#pragma unroll
    for (int dd = 0; dd < 32; dd++)
        q2[dd] = *reinterpret_cast<const unsigned long long*>(qrow + 2 * dd);

    float qt = g_qt[bh * SEQ + i];
    float coshOQ = fmaxf(qt, 1.f + 1e-7f);
    float c_t = fminf(acoshf(coshOQ), 40.f);
    float isOQ = 1.f / sinhf(c_t);
    float Bv = alpha * c_t / (1.f + alpha * c_t);

    float m = -3.4e38f, S = 0.f;
    unsigned long long acc2[32];
#pragma unroll
    for (int dd = 0; dd < 32; dd++) acc2[dd] = 0ull;

    for (int jc = 0; jc < SEQ; jc += CHK) {
        __syncthreads();
        // cooperative chunk load (float4, coalesced)
        for (int idx = tid; idx < CHK * 16; idx += 128) {
            int row = idx >> 4, c4 = idx & 15;
            const float* src = g_Sk + (tokbase + jc + row) * DMODEL + h * HD + c4 * 4;
            *reinterpret_cast<float4*>(kc + row * 64 + c4 * 4) =
                *reinterpret_cast<const float4*>(src);
            const float* srcv = g_vt + (tokbase + jc + row) * DMODEL + h * HD + c4 * 4;
            *reinterpret_cast<float4*>(vc + row * 64 + c4 * 4) =
                *reinterpret_cast<const float4*>(srcv);
        }
        if (tid < CHK) ktc[tid] = g_kt[bh * SEQ + jc + tid];
        __syncthreads();

        for (int j = 0; j < CHK; j++) {
            const unsigned long long* kr =
                reinterpret_cast<const unsigned long long*>(kc + j * 64);
            unsigned long long d2 = 0ull;
#pragma unroll
            for (int dd = 0; dd < 32; dd++) d2 = fma_f32x2(q2[dd], kr[dd], d2);
            float dlo, dhi; unpack_f32x2(d2, dlo, dhi);
            float dot = dlo + dhi;

            float kt = ktc[j];
            float coshOK = fmaxf(kt, 1.f + 1e-7f);
            float raw_cosh = fmaxf(qt * kt - dot, 1.f);
            bool is_self = raw_cosh < 1.f + 1e-5f;
            float safe_cosh = is_self ? 2.f : raw_cosh;
            float t2 = safe_cosh * safe_cosh - 1.f;
            float invs = rsqrtf(t2);
            float sh = t2 * invs;
            float dist = __logf(safe_cosh + sh);
            float rawZ = (raw_cosh * coshOQ - coshOK) * isOQ * invs;
            float Z = is_self ? 1.f : fminf(fmaxf(rawZ, -1.f), 1.f);
            float dL = fminf(dist, 40.f);
            float lp = -lam * __logf(1.f + dL * dL);
            float xe = Bv + Z - 0.1f;
            float ent = __logf(1.f + __expf(xe));
            float l = lp - tau * ent;

            const unsigned long long* vr =
                reinterpret_cast<const unsigned long long*>(vc + j * 64);
            if (l > m) {
                float f = __expf(m - l);          // first iter: exp(-inf)=0
                m = l;
                S = S * f + 1.f;
                unsigned long long f2 = pack_f32x2(f, f);
#pragma unroll
                for (int dd = 0; dd < 32; dd++)
                    acc2[dd] = fma_f32x2(acc2[dd], f2, vr[dd]);
            } else {
                float e = __expf(l - m);
                S += e;
                unsigned long long e2 = pack_f32x2(e, e);
#pragma unroll
                for (int dd = 0; dd < 32; dd++)
                    acc2[dd] = fma_f32x2(vr[dd], e2, acc2[dd]);
            }
        }
    }

    // epilogue: normalize, expmap0, write (all thread-local)
    float inv = 1.f / S;
    float a[64];
    float n2 = 0.f;
#pragma unroll
    for (int dd = 0; dd < 32; dd++) {
        float lo, hi; unpack_f32x2(acc2[dd], lo, hi);
        lo *= inv; hi *= inv;
        a[2 * dd] = lo; a[2 * dd + 1] = hi;
        n2 += lo * lo + hi * hi;
    }
    float nn = sqrtf(n2);
    float tt = coshf(nn);
    float sf = sinhf(nn) / fmaxf(nn, 1e-8f);
    float* orow = g_attncat + (tokbase + i) * LDX + 1 + h * HD;
#pragma unroll
    for (int d = 0; d < 64; d++) orow[d] = a[d] * sf;
    g_attnt[(tokbase + i) * NHEAD + h] = tt;
}

// ---------------- t_new = sqrt(sum_h t_h^2 - 11) ---------------------------
__global__ void attn_time_kernel() {
    int t = blockIdx.x * 256 + threadIdx.x;
    if (t < TOK) {
        float s = 0.f;
#pragma unroll
        for (int hh = 0; hh < NHEAD; hh++) { float a = g_attnt[t * NHEAD + hh]; s += a * a; }
        g_attncat[t * LDX] = sqrtf(s - (float)(NHEAD - 1));
    }
}

// ---------------- residual: res = So + x_s ---------------------------------
__global__ void resid_kernel(const float* __restrict__ x) {
    int idx = blockIdx.x * 256 + threadIdx.x;
    if (idx < TOK * DMODEL) {
        int row = idx / DMODEL, c = idx % DMODEL;
        g_res[idx] = g_Sq[idx] + x[row * LDX + 1 + c];
    }
}

// ---------------- GELU (exact) + add_time over 3072 ------------------------
__global__ __launch_bounds__(256) void gelu_time_kernel() {
    int row = blockIdx.x;
    __shared__ float red[8];
    float ss = 0.f;
    for (int c = threadIdx.x; c < MLP; c += 256) {
        float v = g_Sm[row * MLP + c];
        float ge = 0.5f * v * (1.f + erff(v * 0.70710678118654752f));
        g_h3[row * (MLP + 1) + 1 + c] = ge;
        ss += ge * ge;
    }
    ss = block_sum(ss, red);
    if (threadIdx.x == 0) g_h3[row * (MLP + 1)] = sqrtf(1.f + ss);
}

// ---------------- final: out = add_time(Sm2 + res) -------------------------
__global__ __launch_bounds__(256) void final_kernel(float* __restrict__ out) {
    int row = blockIdx.x;
    __shared__ float red[8];
    float vals[3]; float ss = 0.f;
#pragma unroll
    for (int r = 0; r < 3; r++) {
        int c = threadIdx.x + r * 256;
        float f = g_Sk[row * DMODEL + c] + g_res[row * DMODEL + c];
        vals[r] = f; ss += f * f;
    }
    ss = block_sum(ss, red);
#pragma unroll
    for (int r = 0; r < 3; r++) {
        int c = threadIdx.x + r * 256;
        out[row * LDX + 1 + c] = vals[r];
    }
    if (threadIdx.x == 0) out[row * LDX] = sqrtf(1.f + ss);
}

// ---------------- host -----------------------------------------------------
extern "C" void kernel_launch(void* const* d_in, const int* in_sizes, int n_in,
                              void* d_out, int out_size)
{
    const float* x     = (const float*)d_in[0];
    const float* Wq    = (const float*)d_in[1];
    const float* Wk    = (const float*)d_in[2];
    const float* Wv    = (const float*)d_in[3];
    const float* Wo    = (const float*)d_in[4];
    const float* g1    = (const float*)d_in[5];
    const float* b1    = (const float*)d_in[6];
    const float* g2    = (const float*)d_in[7];
    const float* b2    = (const float*)d_in[8];
    const float* Wm1   = (const float*)d_in[9];
    const float* Wm2   = (const float*)d_in[10];
    const float* alpha = (const float*)d_in[11];
    const float* tau   = (const float*)d_in[12];
    const float* lam   = (const float*)d_in[13];
    float* out = (float*)d_out;

    const int ATTN_SMEM = (2 * CHK * 64 + CHK) * 4;   // 66 KB
    const int GEMM_SMEM = 4 * TILEU * 4;
    cudaFuncSetAttribute(attn_kernel, cudaFuncAttributeMaxDynamicSharedMemorySize, ATTN_SMEM);
    cudaFuncSetAttribute(gemm_tf32_kernel, cudaFuncAttributeMaxDynamicSharedMemorySize, GEMM_SMEM);
    cudaFuncSetAttribute(gemm_tf32_qkv_kernel, cudaFuncAttributeMaxDynamicSharedMemorySize, GEMM_SMEM);

    void *ah0, *aSq, *aSk, *aSv, *aSm, *acat, *ah2, *ah3, *ares;
    cudaGetSymbolAddress(&ah0,  g_h0);
    cudaGetSymbolAddress(&aSq,  g_Sq);
    cudaGetSymbolAddress(&aSk,  g_Sk);
    cudaGetSymbolAddress(&aSv,  g_Sv);
    cudaGetSymbolAddress(&aSm,  g_Sm);
    cudaGetSymbolAddress(&acat, g_attncat);
    cudaGetSymbolAddress(&ah2,  g_h2);
    cudaGetSymbolAddress(&ah3,  g_h3);
    cudaGetSymbolAddress(&ares, g_res);

    // 1. LN1
    ln_rows_kernel<<<TOK, 256>>>(x, LDX, 1, g1, b1, (float*)ah0);

    // 2. QKV projections, one launch (z = q/k/v)
    dim3 gqkv(DMODEL / BN, TOK / BM, 3);
    gemm_tf32_qkv_kernel<<<gqkv, 256, GEMM_SMEM>>>(
        (const float*)ah0, Wq, Wk, Wv, (float*)aSq, (float*)aSk, (float*)aSv);

    // 3. q_t, k_t, v_tan
    qkv_post_kernel<<<NBH * SEQ, 64>>>();

    // 4. attention (128 queries / CTA, one per thread)
    dim3 gattn(SEQ / 128, NBH);
    attn_kernel<<<gattn, 128, ATTN_SMEM>>>(alpha, tau, lam);
    attn_time_kernel<<<(TOK + 255) / 256, 256>>>();

    // 5. output projection (So reuses g_Sq)
    dim3 g768(DMODEL / BN, TOK / BM);
    gemm_tf32_kernel<<<g768, 256, GEMM_SMEM>>>((const float*)acat, Wo, (float*)aSq, LDX, LDX, LDX, DMODEL);

    // 6. residual + LN2
    resid_kernel<<<(TOK * DMODEL + 255) / 256, 256>>>(x);
    ln_rows_kernel<<<TOK, 256>>>((const float*)ares, DMODEL, 0, g2, b2, (float*)ah2);

    // 7. MLP up + GELU + add_time
    dim3 gm1(MLP / BN, TOK / BM);
    gemm_tf32_kernel<<<gm1, 256, GEMM_SMEM>>>((const float*)ah2, Wm1, (float*)aSm, LDX, LDX, LDX, MLP);
    gelu_time_kernel<<<TOK, 256>>>();

    // 8. MLP down (Sm2 reuses g_Sk)
    gemm_tf32_kernel<<<g768, 256, GEMM_SMEM>>>((const float*)ah3, Wm2, (float*)aSk, MLP + 1, MLP + 1, MLP + 1, DMODEL);

    // 9. final residual + add_time
    final_kernel<<<TOK, 256>>>(out);
}